// round 5
// baseline (speedup 1.0000x reference)
#include <cuda_runtime.h>
#include <math.h>

typedef unsigned long long ull;

#define Bb   32
#define Ss   200
#define EDd  256
#define Hh   512
#define NFf  19
#define BSn  (Bb*Ss)          // 6400
#define KP0  288              // padded layer-0 input dim (275 -> 288)
#define K0w  275
#define WSTR 516              // padded smem row stride for W_hh tiles

// ---------------- device scratch (no allocs allowed) ----------------
__device__ float d_INP[(size_t)BSn*KP0];       // [s*B+b][288]
__device__ float d_X  [(size_t)BSn*2048];      // gate preacts (both layers, reused)
__device__ float d_H1 [(size_t)BSn*Hh];        // layer0 outputs, time-major
__device__ float d_H2 [(size_t)BSn*Hh];        // layer1 outputs, time-major
__device__ float d_ht [(size_t)(Ss+1)*Bb*Hh]; // per-step h: [t][b][512]
__device__ unsigned d_bar_count;
__device__ unsigned d_bar_gen;
__device__ float d_loss_sum;
__device__ int   d_mask_cnt;

// ---------------- f32x2 helpers (Blackwell packed fp32) ----------------
__device__ __forceinline__ ull pk2(float x, float y){
    ull r; asm("mov.b64 %0,{%1,%2};" : "=l"(r) : "f"(x), "f"(y)); return r;
}
__device__ __forceinline__ void upk2(ull v, float& x, float& y){
    asm("mov.b64 {%0,%1},%2;" : "=f"(x), "=f"(y) : "l"(v));
}
__device__ __forceinline__ void fma2(ull& d, ull a, ull b){
    asm("fma.rn.f32x2 %0,%1,%2,%0;" : "+l"(d) : "l"(a), "l"(b));
}

__device__ __forceinline__ float sigm(float x){ return 1.f/(1.f+expf(-x)); }

// ---------------- grid barrier (all blocks co-resident) ----------------
__device__ __forceinline__ void gridbar(unsigned target){
    __syncthreads();
    __threadfence();
    if (threadIdx.x == 0) {
        unsigned t = atomicAdd(&d_bar_count, 1u);
        if (t == gridDim.x - 1u) {
            atomicExch(&d_bar_count, 0u);
            atomicExch(&d_bar_gen, target);
        } else {
            volatile unsigned* g = &d_bar_gen;
            while (*g < target) __nanosleep(64);
        }
    }
    __syncthreads();
    __threadfence();
}

__global__ void init_kernel(){
    d_bar_count = 0u; d_bar_gen = 0u;
    d_loss_sum = 0.f; d_mask_cnt = 0;
}
__global__ void reset_bar_kernel(){
    d_bar_count = 0u; d_bar_gen = 0u;
}

// ---------------- fused embedding + scaled features -> INP [s*B+b][288] ----------------
__global__ void feat_kernel(const int* __restrict__ xd,
                            const float* __restrict__ rep,
                            const float* __restrict__ past,
                            const float* __restrict__ seq,
                            const float* __restrict__ Cm,
                            const float* __restrict__ emb)
{
    int warp = threadIdx.x >> 5, lane = threadIdx.x & 31;
    int row = blockIdx.x * 8 + warp;      // row = b*S + s
    int b = row / Ss, s = row - b * Ss;
    int rs = s * Bb + b;                  // time-major storage row
    int tok = xd[row];
    const float4* src = (const float4*)(emb + (size_t)tok * EDd);
    float4* dst = (float4*)(d_INP + (size_t)rs * KP0);
    dst[lane]      = src[lane];
    dst[lane + 32] = src[lane + 32];
    float v = 0.f;
    if (lane < NFf) {
        int base = b * (Ss+1) + s;
        float cf;
        if (lane < 7)       cf = rep [base*7 + lane];
        else if (lane < 13) cf = seq [base*6 + (lane-7)];
        else                cf = past[base*6 + (lane-13)];
        v = Cm[(size_t)row * NFf + lane] * cf;
    }
    d_INP[(size_t)rs * KP0 + EDd + lane] = v;   // 19 features + 13 zero pad
}

// ---------------- batched fp32 GEMM: d_X[m][2048] = A[m][K] * W[2048][Kw]^T + bias ----------------
__global__ void __launch_bounds__(256) gemm_kernel(int whichA,
    const float* __restrict__ W, int Kw, int K,
    const float* __restrict__ b1, const float* __restrict__ b2)
{
    __shared__ float As[16][68];
    __shared__ float Bs[16][68];
    const float* A = whichA ? d_H1 : d_INP;
    int lda = whichA ? Hh : KP0;
    int tid = threadIdx.x;
    int n0 = blockIdx.x * 64, m0 = blockIdx.y * 64;
    int tx = tid & 15, ty = tid >> 4;
    int mi = ty * 4, ni = tx * 4;
    ull acc[4][2];
    #pragma unroll
    for (int i = 0; i < 4; i++) { acc[i][0] = 0ull; acc[i][1] = 0ull; }

    int lmm = tid >> 2, lkq = tid & 3;
    for (int k0 = 0; k0 < K; k0 += 16) {
        float4 av = *(const float4*)&A[(size_t)(m0+lmm)*lda + k0 + lkq*4];
        As[lkq*4+0][lmm] = av.x;
        As[lkq*4+1][lmm] = av.y;
        As[lkq*4+2][lmm] = av.z;
        As[lkq*4+3][lmm] = av.w;
        #pragma unroll
        for (int i = 0; i < 4; i++) {
            int kk = lkq*4 + i;
            int kg = k0 + kk;
            Bs[kk][lmm] = (kg < Kw) ? W[(size_t)(n0+lmm)*Kw + kg] : 0.f;
        }
        __syncthreads();
        #pragma unroll
        for (int k = 0; k < 16; k++) {
            float4 a  = *(float4*)&As[k][mi];
            float4 bv = *(float4*)&Bs[k][ni];
            ull bp0 = pk2(bv.x, bv.y), bp1 = pk2(bv.z, bv.w);
            float am[4] = {a.x, a.y, a.z, a.w};
            #pragma unroll
            for (int i = 0; i < 4; i++) {
                ull ad = pk2(am[i], am[i]);
                fma2(acc[i][0], ad, bp0);
                fma2(acc[i][1], ad, bp1);
            }
        }
        __syncthreads();
    }
    #pragma unroll
    for (int i = 0; i < 4; i++) {
        int m = m0 + mi + i;
        int n = n0 + ni;
        float o0,o1,o2,o3;
        upk2(acc[i][0], o0, o1);
        upk2(acc[i][1], o2, o3);
        float* out = &d_X[(size_t)m*2048 + n];
        out[0] = o0 + b1[n+0] + b2[n+0];
        out[1] = o1 + b1[n+1] + b2[n+1];
        out[2] = o2 + b1[n+2] + b2[n+2];
        out[3] = o3 + b1[n+3] + b2[n+3];
    }
}

// ---------------- persistent recurrent scan: one LSTM layer ----------------
// grid = 128 blocks x 256 threads; block beta owns cell indices m0..m0+3 (4 cells, 4 gates = 16 W rows)
__global__ void __launch_bounds__(256,1) scan_kernel(int layer,
    const float* __restrict__ Whh,
    const float* __restrict__ ih, const float* __restrict__ ic)
{
    extern __shared__ float sm[];
    float* Wsh = sm;                       // [16][WSTR]
    float* hsh = sm + 16*WSTR;             // [32][512]
    float* gsh = hsh + 32*512;             // [16][33]
    float* Hout = layer ? d_H2 : d_H1;
    int tid = threadIdx.x;
    int m0 = blockIdx.x * 4;

    // load the block's 16 W_hh rows into smem (row r = gate*4 + cell)
    for (int i = tid; i < 16*128; i += 256) {
        int r  = i >> 7;
        int kq = (i & 127) * 4;
        int gr = (r >> 2) * 512 + m0 + (r & 3);
        *(float4*)&Wsh[r*WSTR + kq] = *(const float4*)&Whh[(size_t)gr*512 + kq];
    }

    float c_reg = 0.f;
    int ub = tid >> 2, umi = tid & 3;      // tid<128 owns (b=ub, cell=m0+umi)
    if (tid < 128) {
        c_reg = ic[layer*Bb*Hh + ub*Hh + m0 + umi];
        d_ht[(size_t)ub*Hh + m0 + umi] = ih[layer*Bb*Hh + ub*Hh + m0 + umi];
    }
    gridbar(1);

    int row = tid & 15, bsl = tid >> 4;
    int b0 = bsl, b1i = bsl + 16;
    int grow = (row >> 2) * 512 + m0 + (row & 3);

    for (int t = 0; t < Ss; t++) {
        // stage full h[t] into smem
        const float4* hs = (const float4*)&d_ht[(size_t)t*Bb*Hh];
        float4* hd = (float4*)hsh;
        #pragma unroll
        for (int i = 0; i < 16; i++) hd[tid + i*256] = hs[tid + i*256];
        __syncthreads();

        ull a00=0ull, a01=0ull, a10=0ull, a11=0ull;
        const float* wr  = &Wsh[row*WSTR];
        const float* h0p = &hsh[b0*Hh];
        const float* h1p = &hsh[b1i*Hh];
        #pragma unroll 8
        for (int k = 0; k < Hh; k += 4) {
            ull w01 = *(const ull*)&wr[k];
            ull w23 = *(const ull*)&wr[k+2];
            ull x01 = *(const ull*)&h0p[k];
            ull x23 = *(const ull*)&h0p[k+2];
            ull y01 = *(const ull*)&h1p[k];
            ull y23 = *(const ull*)&h1p[k+2];
            fma2(a00, w01, x01); fma2(a01, w23, x23);
            fma2(a10, w01, y01); fma2(a11, w23, y23);
        }
        float p0,p1,p2,p3,q0,q1,q2,q3;
        upk2(a00,p0,p1); upk2(a01,p2,p3);
        upk2(a10,q0,q1); upk2(a11,q2,q3);
        size_t xb = ((size_t)t*Bb)*2048;
        gsh[row*33 + b0 ] = (p0+p1)+(p2+p3) + d_X[xb + (size_t)b0 *2048 + grow];
        gsh[row*33 + b1i] = (q0+q1)+(q2+q3) + d_X[xb + (size_t)b1i*2048 + grow];
        __syncthreads();

        if (tid < 128) {
            float iv = gsh[( 0+umi)*33 + ub];
            float fv = gsh[( 4+umi)*33 + ub];
            float gv = gsh[( 8+umi)*33 + ub];
            float ov = gsh[(12+umi)*33 + ub];
            c_reg = sigm(fv)*c_reg + sigm(iv)*tanhf(gv);
            float h = sigm(ov)*tanhf(c_reg);
            d_ht[(size_t)(t+1)*Bb*Hh + ub*Hh + m0 + umi] = h;
            Hout[((size_t)t*Bb + ub)*Hh + m0 + umi] = h;
        }
        gridbar(t + 2);
    }
}

// ---------------- prediction head: per-row gathered dot + BCE ----------------
__global__ void __launch_bounds__(128) pred_kernel(
    const int* __restrict__ qt, const float* __restrict__ tgt,
    const float* __restrict__ rep, const float* __restrict__ past,
    const float* __restrict__ seq, const float* __restrict__ Cm,
    const float* __restrict__ Wp, const float* __restrict__ bp,
    float* __restrict__ out)
{
    __shared__ float red[4];
    int r = blockIdx.x;
    int b = r / Ss, s = r - b * Ss;
    int q = qt[r];
    const float* wrow = Wp + (size_t)q * (Hh + NFf);
    const float* h2   = d_H2 + ((size_t)s*Bb + b) * Hh;
    int tid = threadIdx.x;
    float p = 0.f;
    for (int k = tid; k < Hh; k += 128) p += wrow[k] * h2[k];
    if (tid < NFf) {
        int base = b * (Ss+1) + (s+1);
        float cf;
        if (tid < 7)       cf = rep [base*7 + tid];
        else if (tid < 13) cf = seq [base*6 + (tid-7)];
        else               cf = past[base*6 + (tid-13)];
        p += wrow[Hh + tid] * (Cm[(size_t)r*NFf + tid] * cf);
    }
    #pragma unroll
    for (int o = 16; o > 0; o >>= 1) p += __shfl_xor_sync(0xffffffffu, p, o);
    if ((tid & 31) == 0) red[tid >> 5] = p;
    __syncthreads();
    if (tid == 0) {
        float x = red[0] + red[1] + red[2] + red[3] + bp[q];
        float m = (q > 0) ? 1.f : 0.f;
        float t = tgt[r];
        if (q > 0) {
            float bce = fmaxf(x, 0.f) - x*t + log1pf(expf(-fabsf(x)));
            atomicAdd(&d_loss_sum, bce);
            atomicAdd(&d_mask_cnt, 1);
        }
        out[1 + r]        = (1.f/(1.f+expf(-x))) * m;
        out[1 + BSn + r]  = t * m;
    }
}

__global__ void fin_kernel(float* __restrict__ out){
    out[0] = d_loss_sum / (float)d_mask_cnt;
}

// ---------------- launch ----------------
extern "C" void kernel_launch(void* const* d_in, const int* in_sizes, int n_in,
                              void* d_out, int out_size)
{
    const int*   x_data = (const int*)  d_in[0];
    const int*   q_t    = (const int*)  d_in[1];
    const float* target = (const float*)d_in[2];
    const float* rep    = (const float*)d_in[3];
    const float* past   = (const float*)d_in[4];
    const float* seq    = (const float*)d_in[5];
    const float* emb    = (const float*)d_in[6];
    const float* Wih0   = (const float*)d_in[7];
    const float* Whh0   = (const float*)d_in[8];
    const float* bih0   = (const float*)d_in[9];
    const float* bhh0   = (const float*)d_in[10];
    const float* Wih1   = (const float*)d_in[11];
    const float* Whh1   = (const float*)d_in[12];
    const float* bih1   = (const float*)d_in[13];
    const float* bhh1   = (const float*)d_in[14];
    const float* Wp     = (const float*)d_in[15];
    const float* bp     = (const float*)d_in[16];
    const float* Cm     = (const float*)d_in[17];
    const float* ih     = (const float*)d_in[18];
    const float* ic     = (const float*)d_in[19];
    float* out = (float*)d_out;

    const int SCAN_SMEM = (16*WSTR + 32*512 + 16*33) * 4;  // 100,672 bytes
    cudaFuncSetAttribute(scan_kernel, cudaFuncAttributeMaxDynamicSharedMemorySize, SCAN_SMEM);

    init_kernel<<<1,1>>>();
    feat_kernel<<<800,256>>>(x_data, rep, past, seq, Cm, emb);
    gemm_kernel<<<dim3(32,100),256>>>(0, Wih0, K0w, KP0, bih0, bhh0);
    scan_kernel<<<128,256,SCAN_SMEM>>>(0, Whh0, ih, ic);
    reset_bar_kernel<<<1,1>>>();
    gemm_kernel<<<dim3(32,100),256>>>(1, Wih1, Hh, Hh, bih1, bhh1);
    scan_kernel<<<128,256,SCAN_SMEM>>>(1, Whh1, ih, ic);
    pred_kernel<<<6400,128>>>(q_t, target, rep, past, seq, Cm, Wp, bp, out);
    fin_kernel<<<1,1>>>(out);
}

// round 7
// speedup vs baseline: 1.0982x; 1.0982x over previous
#include <cuda_runtime.h>
#include <math.h>

typedef unsigned long long ull;

#define Bb   32
#define Ss   200
#define EDd  256
#define Hh   512
#define NFf  19
#define BSn  (Bb*Ss)          // 6400
#define KP0  288              // padded layer-0 input dim (275 -> 288)
#define K0w  275
#define WSTR 516              // padded smem row stride for W_hh tiles
#define HSTR 516              // padded smem row stride for staged h

// ---------------- device scratch (no allocs allowed) ----------------
__device__ float d_INP[(size_t)BSn*KP0];       // [s*B+b][288]
__device__ float d_X  [(size_t)BSn*2048];      // gate preacts (both layers, reused)
__device__ float d_H1 [(size_t)BSn*Hh];        // layer0 outputs, time-major
__device__ float d_H2 [(size_t)BSn*Hh];        // layer1 outputs, time-major
__device__ float d_ht [(size_t)(Ss+1)*Bb*Hh];  // per-step h: [t][b][512]
__device__ unsigned d_bar_count;
__device__ unsigned d_bar_gen;
__device__ float d_loss_sum;
__device__ int   d_mask_cnt;

// ---------------- f32x2 helpers (Blackwell packed fp32) ----------------
__device__ __forceinline__ void upk2(ull v, float& x, float& y){
    asm("mov.b64 {%0,%1},%2;" : "=f"(x), "=f"(y) : "l"(v));
}
__device__ __forceinline__ void fma2(ull& d, ull a, ull b){
    asm("fma.rn.f32x2 %0,%1,%2,%0;" : "+l"(d) : "l"(a), "l"(b));
}
__device__ __forceinline__ ull pk2(float x, float y){
    ull r; asm("mov.b64 %0,{%1,%2};" : "=l"(r) : "f"(x), "f"(y)); return r;
}

__device__ __forceinline__ float sigm(float x){ return 1.f/(1.f+expf(-x)); }

// ---------------- grid barrier (all blocks co-resident) ----------------
__device__ __forceinline__ void gridbar(unsigned target){
    __syncthreads();
    __threadfence();
    if (threadIdx.x == 0) {
        unsigned t = atomicAdd(&d_bar_count, 1u);
        if (t == gridDim.x - 1u) {
            atomicExch(&d_bar_count, 0u);
            atomicExch(&d_bar_gen, target);
        } else {
            volatile unsigned* g = &d_bar_gen;
            while (*g < target) __nanosleep(64);
        }
    }
    __syncthreads();
    __threadfence();
}

__global__ void init_kernel(){
    d_bar_count = 0u; d_bar_gen = 0u;
    d_loss_sum = 0.f; d_mask_cnt = 0;
}

// ---------------- fused embedding + scaled features -> INP [s*B+b][288] ----------------
__global__ void feat_kernel(const int* __restrict__ xd,
                            const float* __restrict__ rep,
                            const float* __restrict__ past,
                            const float* __restrict__ seq,
                            const float* __restrict__ Cm,
                            const float* __restrict__ emb)
{
    int warp = threadIdx.x >> 5, lane = threadIdx.x & 31;
    int row = blockIdx.x * 8 + warp;      // row = b*S + s
    int b = row / Ss, s = row - b * Ss;
    int rs = s * Bb + b;                  // time-major storage row
    int tok = xd[row];
    const float4* src = (const float4*)(emb + (size_t)tok * EDd);
    float4* dst = (float4*)(d_INP + (size_t)rs * KP0);
    dst[lane]      = src[lane];
    dst[lane + 32] = src[lane + 32];
    float v = 0.f;
    if (lane < NFf) {
        int base = b * (Ss+1) + s;
        float cf;
        if (lane < 7)       cf = rep [base*7 + lane];
        else if (lane < 13) cf = seq [base*6 + (lane-7)];
        else                cf = past[base*6 + (lane-13)];
        v = Cm[(size_t)row * NFf + lane] * cf;
    }
    d_INP[(size_t)rs * KP0 + EDd + lane] = v;   // 19 features + 13 zero pad
}

// ---------------- batched fp32 GEMM: d_X[m][2048] = A[m][K] * W[2048][Kw]^T + bias ----------------
__global__ void __launch_bounds__(256) gemm_kernel(int whichA,
    const float* __restrict__ W, int Kw, int K,
    const float* __restrict__ b1, const float* __restrict__ b2)
{
    __shared__ float As[16][68];
    __shared__ float Bs[16][68];
    const float* A = whichA ? d_H1 : d_INP;
    int lda = whichA ? Hh : KP0;
    int tid = threadIdx.x;
    int n0 = blockIdx.x * 64, m0 = blockIdx.y * 64;
    int tx = tid & 15, ty = tid >> 4;
    int mi = ty * 4, ni = tx * 4;
    ull acc[4][2];
    #pragma unroll
    for (int i = 0; i < 4; i++) { acc[i][0] = 0ull; acc[i][1] = 0ull; }

    int lmm = tid >> 2, lkq = tid & 3;
    for (int k0 = 0; k0 < K; k0 += 16) {
        float4 av = *(const float4*)&A[(size_t)(m0+lmm)*lda + k0 + lkq*4];
        As[lkq*4+0][lmm] = av.x;
        As[lkq*4+1][lmm] = av.y;
        As[lkq*4+2][lmm] = av.z;
        As[lkq*4+3][lmm] = av.w;
        #pragma unroll
        for (int i = 0; i < 4; i++) {
            int kk = lkq*4 + i;
            int kg = k0 + kk;
            Bs[kk][lmm] = (kg < Kw) ? W[(size_t)(n0+lmm)*Kw + kg] : 0.f;
        }
        __syncthreads();
        #pragma unroll
        for (int k = 0; k < 16; k++) {
            float4 a  = *(float4*)&As[k][mi];
            float4 bv = *(float4*)&Bs[k][ni];
            ull bp0 = pk2(bv.x, bv.y), bp1 = pk2(bv.z, bv.w);
            float am[4] = {a.x, a.y, a.z, a.w};
            #pragma unroll
            for (int i = 0; i < 4; i++) {
                ull ad = pk2(am[i], am[i]);
                fma2(acc[i][0], ad, bp0);
                fma2(acc[i][1], ad, bp1);
            }
        }
        __syncthreads();
    }
    #pragma unroll
    for (int i = 0; i < 4; i++) {
        int m = m0 + mi + i;
        int n = n0 + ni;
        float o0,o1,o2,o3;
        upk2(acc[i][0], o0, o1);
        upk2(acc[i][1], o2, o3);
        float* out = &d_X[(size_t)m*2048 + n];
        out[0] = o0 + b1[n+0] + b2[n+0];
        out[1] = o1 + b1[n+1] + b2[n+1];
        out[2] = o2 + b1[n+2] + b2[n+2];
        out[3] = o3 + b1[n+3] + b2[n+3];
    }
}

// ---------------- persistent recurrent scan: one LSTM layer ----------------
// 128 blocks x 256 threads; block owns 4 cells (16 W_hh rows).
// Thread = (row 0..15, batch-group 0..7 of 4, k-half 0..1).
// kh is warp-uniform, bg is half-warp-uniform -> h LDS.128 serves 2 addrs (1 cyc),
// W LDS.128 serves 16 addrs (2 cyc). 5 LDS.128 : 8 fma2 per 4-k iter.
__global__ void __launch_bounds__(256,1) scan_kernel(int layer,
    const float* __restrict__ Whh,
    const float* __restrict__ ih, const float* __restrict__ ic,
    unsigned gbase)
{
    extern __shared__ float sm[];
    float* Wsh = sm;                       // [16][WSTR]
    float* hsh = sm + 16*WSTR;             // [32][HSTR]
    float* psh = hsh + 32*HSTR;            // [32][33]  partials [kh*16+row][b]
    float* Hout = layer ? d_H2 : d_H1;
    int tid = threadIdx.x;
    int m0 = blockIdx.x * 4;

    // load the block's 16 W_hh rows into smem (row r = gate*4 + cell)
    for (int i = tid; i < 16*128; i += 256) {
        int r  = i >> 7;
        int kq = (i & 127) << 2;
        int gr = (r >> 2) * 512 + m0 + (r & 3);
        *(float4*)&Wsh[r*WSTR + kq] = *(const float4*)&Whh[(size_t)gr*512 + kq];
    }

    float c_reg = 0.f;
    int ub = tid >> 2, umi = tid & 3;      // tid<128 owns (b=ub, cell=m0+umi)
    if (tid < 128) {
        c_reg = ic[layer*Bb*Hh + ub*Hh + m0 + umi];
        d_ht[(size_t)ub*Hh + m0 + umi] = ih[layer*Bb*Hh + ub*Hh + m0 + umi];
    }
    gridbar(gbase + 1);

    int row = tid & 15;
    int bg  = (tid >> 4) & 7;
    int kh  = tid >> 7;                    // warp-uniform (warps 0-3: 0, warps 4-7: 1)
    int kbase = kh * 256;
    const float* wr  = &Wsh[row*WSTR + kbase];
    const float* hp0 = &hsh[(bg*4+0)*HSTR + kbase];
    const float* hp1 = &hsh[(bg*4+1)*HSTR + kbase];
    const float* hp2 = &hsh[(bg*4+2)*HSTR + kbase];
    const float* hp3 = &hsh[(bg*4+3)*HSTR + kbase];
    float* pout = &psh[(kh*16 + row)*33 + bg*4];

    for (int t = 0; t < Ss; t++) {
        // stage h[t] into padded smem
        {
            const float4* hs = (const float4*)&d_ht[(size_t)t*Bb*Hh];
            #pragma unroll
            for (int i = 0; i < 16; i++) {
                int f = tid + i*256;
                int b = f >> 7, kq = (f & 127) << 2;
                *(float4*)&hsh[b*HSTR + kq] = hs[f];
            }
        }
        __syncthreads();

        ull a0=0ull, a1=0ull, a2=0ull, a3=0ull;
        #pragma unroll 4
        for (int k = 0; k < 256; k += 4) {
            ulonglong2 wv = *(const ulonglong2*)&wr[k];
            ulonglong2 h0 = *(const ulonglong2*)&hp0[k];
            ulonglong2 h1 = *(const ulonglong2*)&hp1[k];
            ulonglong2 h2 = *(const ulonglong2*)&hp2[k];
            ulonglong2 h3 = *(const ulonglong2*)&hp3[k];
            fma2(a0, wv.x, h0.x); fma2(a0, wv.y, h0.y);
            fma2(a1, wv.x, h1.x); fma2(a1, wv.y, h1.y);
            fma2(a2, wv.x, h2.x); fma2(a2, wv.y, h2.y);
            fma2(a3, wv.x, h3.x); fma2(a3, wv.y, h3.y);
        }
        float u0,u1;
        upk2(a0,u0,u1); pout[0] = u0+u1;
        upk2(a1,u0,u1); pout[1] = u0+u1;
        upk2(a2,u0,u1); pout[2] = u0+u1;
        upk2(a3,u0,u1); pout[3] = u0+u1;
        __syncthreads();

        if (tid < 128) {
            size_t xr = ((size_t)t*Bb + ub)*2048 + m0 + umi;
            float iv = psh[( 0+umi)*33+ub] + psh[(16+ 0+umi)*33+ub] + d_X[xr];
            float fv = psh[( 4+umi)*33+ub] + psh[(16+ 4+umi)*33+ub] + d_X[xr+512];
            float gv = psh[( 8+umi)*33+ub] + psh[(16+ 8+umi)*33+ub] + d_X[xr+1024];
            float ov = psh[(12+umi)*33+ub] + psh[(16+12+umi)*33+ub] + d_X[xr+1536];
            c_reg = sigm(fv)*c_reg + sigm(iv)*tanhf(gv);
            float h = sigm(ov)*tanhf(c_reg);
            d_ht[(size_t)(t+1)*Bb*Hh + ub*Hh + m0 + umi] = h;
            Hout[((size_t)t*Bb + ub)*Hh + m0 + umi] = h;
        }
        gridbar(gbase + t + 2);
    }
}

// ---------------- prediction head: per-row gathered dot + BCE ----------------
__global__ void __launch_bounds__(128) pred_kernel(
    const int* __restrict__ qt, const float* __restrict__ tgt,
    const float* __restrict__ rep, const float* __restrict__ past,
    const float* __restrict__ seq, const float* __restrict__ Cm,
    const float* __restrict__ Wp, const float* __restrict__ bp,
    float* __restrict__ out)
{
    __shared__ float red[4];
    int r = blockIdx.x;
    int b = r / Ss, s = r - b * Ss;
    int q = qt[r];
    const float* wrow = Wp + (size_t)q * (Hh + NFf);
    const float* h2   = d_H2 + ((size_t)s*Bb + b) * Hh;
    int tid = threadIdx.x;
    float p = 0.f;
    for (int k = tid; k < Hh; k += 128) p += wrow[k] * h2[k];
    if (tid < NFf) {
        int base = b * (Ss+1) + (s+1);
        float cf;
        if (tid < 7)       cf = rep [base*7 + tid];
        else if (tid < 13) cf = seq [base*6 + (tid-7)];
        else               cf = past[base*6 + (tid-13)];
        p += wrow[Hh + tid] * (Cm[(size_t)r*NFf + tid] * cf);
    }
    #pragma unroll
    for (int o = 16; o > 0; o >>= 1) p += __shfl_xor_sync(0xffffffffu, p, o);
    if ((tid & 31) == 0) red[tid >> 5] = p;
    __syncthreads();
    if (tid == 0) {
        float x = red[0] + red[1] + red[2] + red[3] + bp[q];
        float m = (q > 0) ? 1.f : 0.f;
        float t = tgt[r];
        if (q > 0) {
            float bce = fmaxf(x, 0.f) - x*t + log1pf(expf(-fabsf(x)));
            atomicAdd(&d_loss_sum, bce);
            atomicAdd(&d_mask_cnt, 1);
        }
        out[1 + r]        = (1.f/(1.f+expf(-x))) * m;
        out[1 + BSn + r]  = t * m;
    }
}

__global__ void fin_kernel(float* __restrict__ out){
    out[0] = d_loss_sum / (float)d_mask_cnt;
}

// ---------------- launch ----------------
extern "C" void kernel_launch(void* const* d_in, const int* in_sizes, int n_in,
                              void* d_out, int out_size)
{
    const int*   x_data = (const int*)  d_in[0];
    const int*   q_t    = (const int*)  d_in[1];
    const float* target = (const float*)d_in[2];
    const float* rep    = (const float*)d_in[3];
    const float* past   = (const float*)d_in[4];
    const float* seq    = (const float*)d_in[5];
    const float* emb    = (const float*)d_in[6];
    const float* Wih0   = (const float*)d_in[7];
    const float* Whh0   = (const float*)d_in[8];
    const float* bih0   = (const float*)d_in[9];
    const float* bhh0   = (const float*)d_in[10];
    const float* Wih1   = (const float*)d_in[11];
    const float* Whh1   = (const float*)d_in[12];
    const float* bih1   = (const float*)d_in[13];
    const float* bhh1   = (const float*)d_in[14];
    const float* Wp     = (const float*)d_in[15];
    const float* bp     = (const float*)d_in[16];
    const float* Cm     = (const float*)d_in[17];
    const float* ih     = (const float*)d_in[18];
    const float* ic     = (const float*)d_in[19];
    float* out = (float*)d_out;

    const int SCAN_SMEM = (16*WSTR + 32*HSTR + 32*33) * 4;  // 103,296 bytes
    cudaFuncSetAttribute(scan_kernel, cudaFuncAttributeMaxDynamicSharedMemorySize, SCAN_SMEM);

    init_kernel<<<1,1>>>();
    feat_kernel<<<800,256>>>(x_data, rep, past, seq, Cm, emb);
    gemm_kernel<<<dim3(32,100),256>>>(0, Wih0, K0w, KP0, bih0, bhh0);
    scan_kernel<<<128,256,SCAN_SMEM>>>(0, Whh0, ih, ic, 0u);
    gemm_kernel<<<dim3(32,100),256>>>(1, Wih1, Hh, Hh, bih1, bhh1);
    scan_kernel<<<128,256,SCAN_SMEM>>>(1, Whh1, ih, ic, (unsigned)(Ss+1));
    pred_kernel<<<6400,128>>>(q_t, target, rep, past, seq, Cm, Wp, bp, out);
    fin_kernel<<<1,1>>>(out);
}